// round 14
// baseline (speedup 1.0000x reference)
#include <cuda_runtime.h>
#include <cuda_fp16.h>
#include <math.h>
#include <stdint.h>

#define NN      50000
#define IN_DIM  128
#define OUT_DIM 32
#define HEADS   8
#define FF      256          // OUT_DIM * HEADS
#define EE      800000
#define SEM_HID 128
#define NCHUNK  49           // ceil(NN / 1024)

// ---------------- scratch (static device globals; no allocation) -------------
__device__ __half g_feat16[2][NN * FF];    // W-projected features (fp16, agg-only)
__device__ __half g_z16[2][NN * FF];       // z (fp16) = ELU(agg + bias)
__device__ float  g_el[2][NN * HEADS];
__device__ float  g_er[2][NN * HEADS];
__device__ int    g_csrc[2][EE];           // CSR src node per slot
__device__ int    g_rowptr[2][NN + 1];
__device__ int    g_cnt[2][NN];            // zero-init at load; re-zeroed by scanapply
__device__ int    g_cursor[2][NN];
__device__ int    g_bsum[2][NCHUNK];
__device__ float  g_qsum[2];               // zero-init at load; re-zeroed by count

// ---------------- mma helpers -------------------------------------------------
__device__ __forceinline__ uint32_t f2tf32(float x) {
    uint32_t r;
    asm("cvt.rna.tf32.f32 %0, %1;" : "=r"(r) : "f"(x));
    return r;
}
__device__ __forceinline__ void mma_tf32(float c[4],
                                         uint32_t a0, uint32_t a1, uint32_t a2, uint32_t a3,
                                         uint32_t b0, uint32_t b1) {
    asm volatile(
        "mma.sync.aligned.m16n8k8.row.col.f32.tf32.tf32.f32 "
        "{%0,%1,%2,%3}, {%4,%5,%6,%7}, {%8,%9}, {%0,%1,%2,%3};\n"
        : "+f"(c[0]), "+f"(c[1]), "+f"(c[2]), "+f"(c[3])
        : "r"(a0), "r"(a1), "r"(a2), "r"(a3), "r"(b0), "r"(b1));
}
__device__ __forceinline__ void mma_f16(float c[4],
                                        uint32_t a0, uint32_t a1, uint32_t a2, uint32_t a3,
                                        uint32_t b0, uint32_t b1) {
    asm volatile(
        "mma.sync.aligned.m16n8k16.row.col.f32.f16.f16.f32 "
        "{%0,%1,%2,%3}, {%4,%5,%6,%7}, {%8,%9}, {%0,%1,%2,%3};\n"
        : "+f"(c[0]), "+f"(c[1]), "+f"(c[2]), "+f"(c[3])
        : "r"(a0), "r"(a1), "r"(a2), "r"(a3), "r"(b0), "r"(b1));
}
__device__ __forceinline__ float tanh_fast(float x) {
    float r;
    asm("tanh.approx.f32 %0, %1;" : "=f"(r) : "f"(x));
    return r;
}
__device__ __forceinline__ void group_bar(int id) {
    asm volatile("bar.sync %0, 64;" :: "r"(id) : "memory");
}

// ---------------- K1: tf32 GEMM  feat = h @ [W_a|W_b]  + fused el/er ---------
#define GBM 128
#define GBN 64
#define GBK 16
#define APAD 8
#define BPAD 8
__global__ __launch_bounds__(256) void gemm1_kernel(
    const float* __restrict__ h,
    const float* __restrict__ Wa,
    const float* __restrict__ Wb,
    const float* __restrict__ al_a,
    const float* __restrict__ ar_a,
    const float* __restrict__ al_b,
    const float* __restrict__ ar_b) {
    __shared__ uint32_t As[GBK][GBM + APAD];
    __shared__ uint32_t Bs[GBK][GBN + BPAD];
    const int tid = threadIdx.x;
    const int lane = tid & 31;
    const int wid = tid >> 5;
    const int mBase = (wid >> 1) * 32;
    const int nBase = (wid & 1) * 32;
    const int rowBase = blockIdx.y * GBM;
    const int colBase = blockIdx.x * GBN;

    float acc[2][4][4];
#pragma unroll
    for (int mf = 0; mf < 2; mf++)
#pragma unroll
        for (int nf = 0; nf < 4; nf++)
#pragma unroll
            for (int c = 0; c < 4; c++) acc[mf][nf][c] = 0.0f;

    for (int k0 = 0; k0 < IN_DIM; k0 += GBK) {
#pragma unroll
        for (int it = 0; it < 2; it++) {
            int idx = tid + it * 256;
            int r = idx >> 2, c4 = idx & 3;
            int gr = rowBase + r;
            float4 v = make_float4(0.f, 0.f, 0.f, 0.f);
            if (gr < NN) v = *(const float4*)&h[gr * IN_DIM + k0 + c4 * 4];
            As[c4 * 4 + 0][r] = f2tf32(v.x);
            As[c4 * 4 + 1][r] = f2tf32(v.y);
            As[c4 * 4 + 2][r] = f2tf32(v.z);
            As[c4 * 4 + 3][r] = f2tf32(v.w);
        }
        {
            int r = tid >> 4, c4 = tid & 15;
            int gc = colBase + c4 * 4;
            const float* W = (gc >= FF) ? Wb : Wa;
            int cc = gc & (FF - 1);
            float4 v = *(const float4*)&W[(k0 + r) * FF + cc];
            Bs[r][c4 * 4 + 0] = f2tf32(v.x);
            Bs[r][c4 * 4 + 1] = f2tf32(v.y);
            Bs[r][c4 * 4 + 2] = f2tf32(v.z);
            Bs[r][c4 * 4 + 3] = f2tf32(v.w);
        }
        __syncthreads();
#pragma unroll
        for (int ks = 0; ks < GBK; ks += 8) {
            uint32_t a[2][4], b[4][2];
#pragma unroll
            for (int mf = 0; mf < 2; mf++) {
                int row = mBase + mf * 16 + (lane >> 2);
                a[mf][0] = As[ks + (lane & 3)][row];
                a[mf][1] = As[ks + (lane & 3)][row + 8];
                a[mf][2] = As[ks + 4 + (lane & 3)][row];
                a[mf][3] = As[ks + 4 + (lane & 3)][row + 8];
            }
#pragma unroll
            for (int nf = 0; nf < 4; nf++) {
                int col = nBase + nf * 8 + (lane >> 2);
                b[nf][0] = Bs[ks + (lane & 3)][col];
                b[nf][1] = Bs[ks + 4 + (lane & 3)][col];
            }
#pragma unroll
            for (int mf = 0; mf < 2; mf++)
#pragma unroll
                for (int nf = 0; nf < 4; nf++)
                    mma_tf32(acc[mf][nf], a[mf][0], a[mf][1], a[mf][2], a[mf][3],
                             b[nf][0], b[nf][1]);
        }
        __syncthreads();
    }

    // ---- epilogue: write feat (fp16) + fused el/er (warp N-span == one head)
    const int gc0 = colBase + nBase;          // 32-aligned
    const int hg = gc0 >> 5;                  // global head 0..15
    const int p = hg >> 3;
    const int hd = hg & 7;
    const float* al = p ? al_b : al_a;
    const float* ar = p ? ar_b : ar_a;
    float alv[8], arv[8];
#pragma unroll
    for (int nf = 0; nf < 4; nf++) {
        int c = nf * 8 + 2 * (lane & 3);
        alv[nf * 2 + 0] = al[hd * OUT_DIM + c];
        alv[nf * 2 + 1] = al[hd * OUT_DIM + c + 1];
        arv[nf * 2 + 0] = ar[hd * OUT_DIM + c];
        arv[nf * 2 + 1] = ar[hd * OUT_DIM + c + 1];
    }
    const int ccBase = gc0 & 255;
#pragma unroll
    for (int mf = 0; mf < 2; mf++) {
#pragma unroll
        for (int half = 0; half < 2; half++) {
            int gr = rowBase + mBase + mf * 16 + half * 8 + (lane >> 2);
            float el = 0.0f, er = 0.0f;
            if (gr < NN) {
#pragma unroll
                for (int nf = 0; nf < 4; nf++) {
                    float v0 = acc[mf][nf][half * 2 + 0];
                    float v1 = acc[mf][nf][half * 2 + 1];
                    int cc = ccBase + nf * 8 + 2 * (lane & 3);
                    *(__half2*)&g_feat16[p][gr * FF + cc] = __floats2half2_rn(v0, v1);
                    el += v0 * alv[nf * 2] + v1 * alv[nf * 2 + 1];
                    er += v0 * arv[nf * 2] + v1 * arv[nf * 2 + 1];
                }
            }
            el += __shfl_xor_sync(0xffffffffu, el, 1);
            el += __shfl_xor_sync(0xffffffffu, el, 2);
            er += __shfl_xor_sync(0xffffffffu, er, 1);
            er += __shfl_xor_sync(0xffffffffu, er, 2);
            if ((lane & 3) == 0 && gr < NN) {
                g_el[p][gr * HEADS + hd] = el;
                g_er[p][gr * HEADS + hd] = er;
            }
        }
    }
}

// ---------------- K3: degree histogram (+ qsum reset) ------------------------
__global__ void count_kernel(const int* __restrict__ dst_a,
                             const int* __restrict__ dst_b) {
    int i = blockIdx.x * blockDim.x + threadIdx.x;
    if (i < 2) g_qsum[i] = 0.0f;          // reset for this replay (precedes gemm2)
    if (i >= 2 * EE) return;
    int p = (i >= EE) ? 1 : 0;
    int e = i - p * EE;
    int d = p ? dst_b[e] : dst_a[e];
    atomicAdd(&g_cnt[p][d], 1);
}

// ---------------- K4a: per-chunk reduce --------------------------------------
__global__ __launch_bounds__(256) void reduce_kernel() {
    int p = blockIdx.y, c = blockIdx.x, t = threadIdx.x;
    int base = c * 1024;
    int v = 0;
#pragma unroll
    for (int k = 0; k < 4; k++) {
        int i = base + t + k * 256;
        if (i < NN) v += g_cnt[p][i];
    }
    __shared__ int sh[256];
    sh[t] = v;
    __syncthreads();
#pragma unroll
    for (int st = 128; st > 0; st >>= 1) {
        if (t < st) sh[t] += sh[t + st];
        __syncthreads();
    }
    if (t == 0) g_bsum[p][c] = sh[0];
}

// ---------------- K4b: tiny serial scan of chunk sums ------------------------
__global__ void bscan_kernel() {
    int p = blockIdx.x;
    if (threadIdx.x != 0) return;
    int run = 0;
    for (int c = 0; c < NCHUNK; c++) {
        int tmp = g_bsum[p][c];
        g_bsum[p][c] = run;
        run += tmp;
    }
}

// ---------------- K4c: scan apply -> rowptr + cursor (+ cnt reset) -----------
__global__ __launch_bounds__(1024) void scanapply_kernel() {
    int p = blockIdx.y, c = blockIdx.x, t = threadIdx.x;
    int i = c * 1024 + t;
    int v = (i < NN) ? g_cnt[p][i] : 0;
    int lane = t & 31, w = t >> 5;
    int x = v;
#pragma unroll
    for (int o = 1; o < 32; o <<= 1) {
        int y = __shfl_up_sync(0xffffffffu, x, o);
        if (lane >= o) x += y;
    }
    __shared__ int ws[32];
    if (lane == 31) ws[w] = x;
    __syncthreads();
    if (w == 0) {
        int y = ws[lane];
#pragma unroll
        for (int o = 1; o < 32; o <<= 1) {
            int z = __shfl_up_sync(0xffffffffu, y, o);
            if (lane >= o) y += z;
        }
        ws[lane] = y;
    }
    __syncthreads();
    int incl = x + ((w > 0) ? ws[w - 1] : 0) + g_bsum[p][c];
    if (i < NN) {
        g_rowptr[p][i + 1] = incl;
        g_cursor[p][i]     = incl - v;
        g_cnt[p][i]        = 0;           // reset for next replay
    }
    if (i == 0) g_rowptr[p][0] = 0;
}

// ---------------- K5: scatter into CSR (slim: cursor + csrc only) ------------
__global__ void scatter_kernel(const int* __restrict__ src_a,
                               const int* __restrict__ dst_a,
                               const int* __restrict__ src_b,
                               const int* __restrict__ dst_b) {
    int i = blockIdx.x * blockDim.x + threadIdx.x;
    if (i >= 2 * EE) return;
    int p = (i >= EE) ? 1 : 0;
    int e = i - p * EE;
    int s = p ? src_b[e] : src_a[e];
    int d = p ? dst_b[e] : dst_a[e];
    int pos = atomicAdd(&g_cursor[p][d], 1);
    g_csrc[p][pos] = s;
}

// ---------------- K6: per-dst aggregation (chunked, smem-staged) -------------
// 128 threads; 2 dst-groups of 64 threads; named barriers per group.
// Per chunk of <=64 edges: coop-load csrc, compute ex (1 el-load per edge-head),
// then pure gather-MAC with addresses/weights from smem.
__global__ __launch_bounds__(128) void agg_kernel(const float* __restrict__ bias_a,
                                                  const float* __restrict__ bias_b) {
    __shared__ int   sidx[2][64];
    __shared__ float sex[2][64 * 8];
    __shared__ float ser[2][8];

    const int g = threadIdx.x >> 6;          // group 0/1
    const int d = blockIdx.x * 2 + g;
    const int p = blockIdx.y;
    const int t = threadIdx.x & 63;          // 0..63 within group
    const int barid = g + 1;                 // named barrier 1 or 2
    const int start = g_rowptr[p][d];
    const int end   = g_rowptr[p][d + 1];
    const int hd = t >> 3;                   // head for cols [t*4, t*4+4)
    const int hd8 = t & 7;                   // head for phase A

    if (t < 8) ser[g][t] = g_er[p][d * HEADS + t];

    const __half* fbase  = &g_feat16[p][0];
    const float*  elbase = &g_el[p][0];
    const int*    csrc   = &g_csrc[p][0];

    float4 acc = make_float4(0.f, 0.f, 0.f, 0.f);
    float den = 0.0f;

    for (int cs = start; cs < end; cs += 64) {
        const int n = min(64, end - cs);
        if (t < n) sidx[g][t] = csrc[cs + t];
        group_bar(barid);

        // phase A: ex for 8 edges x 8 heads per pass
        {
            float erh = ser[g][hd8];
            for (int e = t >> 3; e < n; e += 8) {
                int s = sidx[g][e];
                float x = __ldg(&elbase[s * HEADS + hd8]) + erh;
                x = (x > 0.0f) ? x : 0.2f * x;       // leaky_relu(0.2)
                sex[g][e * 8 + hd8] = __expf(x);
            }
        }
        group_bar(barid);

        // phase B: gather-MAC
        int e = 0;
        for (; e + 1 < n; e += 2) {
            int s0 = sidx[g][e];
            int s1 = sidx[g][e + 1];
            float ex0 = sex[g][e * 8 + hd];
            float ex1 = sex[g][(e + 1) * 8 + hd];
            uint2 r0 = *(const uint2*)&fbase[s0 * FF + t * 4];
            uint2 r1 = *(const uint2*)&fbase[s1 * FF + t * 4];
            den += ex0 + ex1;
            float2 a0 = __half22float2(*(const __half2*)&r0.x);
            float2 b0 = __half22float2(*(const __half2*)&r0.y);
            float2 a1 = __half22float2(*(const __half2*)&r1.x);
            float2 b1 = __half22float2(*(const __half2*)&r1.y);
            acc.x += a0.x * ex0 + a1.x * ex1;
            acc.y += a0.y * ex0 + a1.y * ex1;
            acc.z += b0.x * ex0 + b1.x * ex1;
            acc.w += b0.y * ex0 + b1.y * ex1;
        }
        if (e < n) {
            int s0 = sidx[g][e];
            float ex0 = sex[g][e * 8 + hd];
            uint2 r0 = *(const uint2*)&fbase[s0 * FF + t * 4];
            den += ex0;
            float2 a0 = __half22float2(*(const __half2*)&r0.x);
            float2 b0 = __half22float2(*(const __half2*)&r0.y);
            acc.x += a0.x * ex0;
            acc.y += a0.y * ex0;
            acc.z += b0.x * ex0;
            acc.w += b0.y * ex0;
        }
        group_bar(barid);                    // guard sidx/sex reuse next chunk
    }

    float invd = (den > 0.0f) ? 1.0f / den : 1.0f;
    const float* bias = p ? bias_b : bias_a;
    float4 bv = *(const float4*)&bias[t * 4];
    float4 z;
    z.x = acc.x * invd + bv.x;
    z.y = acc.y * invd + bv.y;
    z.z = acc.z * invd + bv.z;
    z.w = acc.w * invd + bv.w;
    z.x = (z.x > 0.0f) ? z.x : (expf(z.x) - 1.0f);
    z.y = (z.y > 0.0f) ? z.y : (expf(z.y) - 1.0f);
    z.z = (z.z > 0.0f) ? z.z : (expf(z.z) - 1.0f);
    z.w = (z.w > 0.0f) ? z.w : (expf(z.w) - 1.0f);
    uint2 zo;
    *(__half2*)&zo.x = __floats2half2_rn(z.x, z.y);
    *(__half2*)&zo.y = __floats2half2_rn(z.z, z.w);
    *(uint2*)&g_z16[p][d * FF + t * 4] = zo;
}

// ---------------- K7: fp16 GEMM  q = Z @ Wsem  + fused tanh.wsem reduce ------
#define BK2   32
#define APAD2 8
#define BPAD2 8
__global__ __launch_bounds__(256) void gemm2_kernel(
    const float* __restrict__ Wsem,
    const float* __restrict__ bsem,
    const float* __restrict__ wsem) {
    __shared__ __half As[GBM][BK2 + APAD2];   // m-major
    __shared__ __half Bs[GBN][BK2 + BPAD2];   // n-major (transposed fill)
    const __half* Z = (const __half*)g_z16;
    const int M = 2 * NN;
    const int tid = threadIdx.x;
    const int lane = tid & 31;
    const int wid = tid >> 5;
    const int mBase = (wid >> 1) * 32;
    const int nBase = (wid & 1) * 32;
    const int rowBase = blockIdx.y * GBM;
    const int colBase = blockIdx.x * GBN;

    float acc[2][4][4];
#pragma unroll
    for (int mf = 0; mf < 2; mf++)
#pragma unroll
        for (int nf = 0; nf < 4; nf++)
#pragma unroll
            for (int c = 0; c < 4; c++) acc[mf][nf][c] = 0.0f;

    for (int k0 = 0; k0 < FF; k0 += BK2) {
#pragma unroll
        for (int it = 0; it < 2; it++) {
            int idx = tid + it * 256;
            int r = idx >> 2, q = idx & 3;
            int gr = rowBase + r;
            uint4 v = make_uint4(0u, 0u, 0u, 0u);
            if (gr < M) v = *(const uint4*)&Z[gr * FF + k0 + q * 8];
            *(uint4*)&As[r][q * 8] = v;
        }
#pragma unroll
        for (int it = 0; it < 2; it++) {
            int slot = tid * 2 + it;
            int r = slot >> 4, c4 = slot & 15;
            float4 v = *(const float4*)&Wsem[(k0 + r) * SEM_HID + colBase + c4 * 4];
            Bs[c4 * 4 + 0][r] = __float2half_rn(v.x);
            Bs[c4 * 4 + 1][r] = __float2half_rn(v.y);
            Bs[c4 * 4 + 2][r] = __float2half_rn(v.z);
            Bs[c4 * 4 + 3][r] = __float2half_rn(v.w);
        }
        __syncthreads();
#pragma unroll
        for (int ks = 0; ks < BK2; ks += 16) {
            uint32_t a[2][4], b[4][2];
#pragma unroll
            for (int mf = 0; mf < 2; mf++) {
                int row = mBase + mf * 16 + (lane >> 2);
                int kc = ks + 2 * (lane & 3);
                a[mf][0] = *(const uint32_t*)&As[row][kc];
                a[mf][1] = *(const uint32_t*)&As[row + 8][kc];
                a[mf][2] = *(const uint32_t*)&As[row][kc + 8];
                a[mf][3] = *(const uint32_t*)&As[row + 8][kc + 8];
            }
#pragma unroll
            for (int nf = 0; nf < 4; nf++) {
                int col = nBase + nf * 8 + (lane >> 2);
                int kc = ks + 2 * (lane & 3);
                b[nf][0] = *(const uint32_t*)&Bs[col][kc];
                b[nf][1] = *(const uint32_t*)&Bs[col][kc + 8];
            }
#pragma unroll
            for (int mf = 0; mf < 2; mf++)
#pragma unroll
                for (int nf = 0; nf < 4; nf++)
                    mma_f16(acc[mf][nf], a[mf][0], a[mf][1], a[mf][2], a[mf][3],
                            b[nf][0], b[nf][1]);
        }
        __syncthreads();
    }

    // ---- epilogue: tanh(q + bsem) . wsem, reduce, atomic into g_qsum --------
    float bsv[8], wsv[8];
#pragma unroll
    for (int nf = 0; nf < 4; nf++) {
        int gc = colBase + nBase + nf * 8 + 2 * (lane & 3);
        bsv[nf * 2 + 0] = bsem[gc];
        bsv[nf * 2 + 1] = bsem[gc + 1];
        wsv[nf * 2 + 0] = wsem[gc];
        wsv[nf * 2 + 1] = wsem[gc + 1];
    }
    float sp0 = 0.0f, sp1 = 0.0f;
#pragma unroll
    for (int mf = 0; mf < 2; mf++) {
#pragma unroll
        for (int half = 0; half < 2; half++) {
            int gr = rowBase + mBase + mf * 16 + half * 8 + (lane >> 2);
            if (gr < M) {
                float rs = 0.0f;
#pragma unroll
                for (int nf = 0; nf < 4; nf++) {
                    rs += tanh_fast(acc[mf][nf][half * 2 + 0] + bsv[nf * 2 + 0]) * wsv[nf * 2 + 0];
                    rs += tanh_fast(acc[mf][nf][half * 2 + 1] + bsv[nf * 2 + 1]) * wsv[nf * 2 + 1];
                }
                if (gr < NN) sp0 += rs; else sp1 += rs;
            }
        }
    }
#pragma unroll
    for (int o = 16; o > 0; o >>= 1) {
        sp0 += __shfl_down_sync(0xffffffffu, sp0, o);
        sp1 += __shfl_down_sync(0xffffffffu, sp1, o);
    }
    __shared__ float sh[8][2];
    if (lane == 0) { sh[wid][0] = sp0; sh[wid][1] = sp1; }
    __syncthreads();
    if (tid == 0) {
        float s0 = 0.f, s1 = 0.f;
#pragma unroll
        for (int k = 0; k < 8; k++) { s0 += sh[k][0]; s1 += sh[k][1]; }
        if (s0 != 0.0f) atomicAdd(&g_qsum[0], s0);
        if (s1 != 0.0f) atomicAdd(&g_qsum[1], s1);
    }
}

// ---------------- K9: combine with semantic softmax (fp16 z -> fp32 out) -----
__global__ void combine_kernel(float4* __restrict__ out) {
    int i = blockIdx.x * blockDim.x + threadIdx.x;
    if (i >= NN * FF / 4) return;
    float q0 = g_qsum[0] * (1.0f / NN);
    float q1 = g_qsum[1] * (1.0f / NN);
    float mx = fmaxf(q0, q1);
    float b0 = __expf(q0 - mx);
    float b1 = __expf(q1 - mx);
    float inv = 1.0f / (b0 + b1);
    b0 *= inv; b1 *= inv;
    uint2 u0 = *(const uint2*)&g_z16[0][i * 4];
    uint2 u1 = *(const uint2*)&g_z16[1][i * 4];
    float2 a0 = __half22float2(*(const __half2*)&u0.x);
    float2 a1 = __half22float2(*(const __half2*)&u0.y);
    float2 c0 = __half22float2(*(const __half2*)&u1.x);
    float2 c1 = __half22float2(*(const __half2*)&u1.y);
    float4 r;
    r.x = a0.x * b0 + c0.x * b1;
    r.y = a0.y * b0 + c0.y * b1;
    r.z = a1.x * b0 + c1.x * b1;
    r.w = a1.y * b0 + c1.y * b1;
    out[i] = r;
}

// ---------------- launch -----------------------------------------------------
extern "C" void kernel_launch(void* const* d_in, const int* in_sizes, int n_in,
                              void* d_out, int out_size) {
    const float* h      = (const float*)d_in[0];
    const int*   src_a  = (const int*)  d_in[1];
    const int*   dst_a  = (const int*)  d_in[2];
    const int*   src_b  = (const int*)  d_in[3];
    const int*   dst_b  = (const int*)  d_in[4];
    const float* W_a    = (const float*)d_in[5];
    const float* al_a   = (const float*)d_in[6];
    const float* ar_a   = (const float*)d_in[7];
    const float* bias_a = (const float*)d_in[8];
    const float* W_b    = (const float*)d_in[9];
    const float* al_b   = (const float*)d_in[10];
    const float* ar_b   = (const float*)d_in[11];
    const float* bias_b = (const float*)d_in[12];
    const float* Wsem   = (const float*)d_in[13];
    const float* bsem   = (const float*)d_in[14];
    const float* wsem   = (const float*)d_in[15];
    float* out = (float*)d_out;

    (void)in_sizes; (void)n_in; (void)out_size;

    // One-time creation of side stream + events (host objects, no device mem).
    static cudaStream_t s2 = nullptr;
    static cudaEvent_t ev_fork = nullptr, ev_join = nullptr;
    if (s2 == nullptr) {
        cudaStreamCreateWithFlags(&s2, cudaStreamNonBlocking);
        cudaEventCreateWithFlags(&ev_fork, cudaEventDisableTiming);
        cudaEventCreateWithFlags(&ev_join, cudaEventDisableTiming);
    }

    // ---- fork: CSR build on s2, projection GEMM on main stream --------------
    cudaEventRecord(ev_fork, 0);
    cudaStreamWaitEvent(s2, ev_fork, 0);

    // s2 branch: count -> scan -> scatter (depends only on edge lists)
    count_kernel<<<(2 * EE + 255) / 256, 256, 0, s2>>>(dst_a, dst_b);
    {
        dim3 grid(NCHUNK, 2);
        reduce_kernel<<<grid, 256, 0, s2>>>();
        bscan_kernel<<<2, 32, 0, s2>>>();
        scanapply_kernel<<<grid, 1024, 0, s2>>>();
    }
    scatter_kernel<<<(2 * EE + 255) / 256, 256, 0, s2>>>(src_a, dst_a, src_b, dst_b);
    cudaEventRecord(ev_join, s2);

    // main branch: projection GEMM (tf32 TC) + fused el/er
    {
        dim3 grid((2 * FF) / GBN, (NN + GBM - 1) / GBM);
        gemm1_kernel<<<grid, 256>>>(h, W_a, W_b, al_a, ar_a, al_b, ar_b);
    }

    // ---- join ----------------------------------------------------------------
    cudaStreamWaitEvent(0, ev_join, 0);

    {   // gather aggregation + softmax + bias + ELU (2 dst-groups per block)
        dim3 grid(NN / 2, 2);
        agg_kernel<<<grid, 128>>>(bias_a, bias_b);
    }

    {   // semantic GEMM (fp16 TC) + fused tanh.wsem reduction
        dim3 grid(SEM_HID / GBN, (2 * NN + GBM - 1) / GBM);
        gemm2_kernel<<<grid, 256>>>(Wsem, bsem, wsem);
    }

    combine_kernel<<<(NN * FF / 4 + 255) / 256, 256>>>((float4*)out);
}

// round 15
// speedup vs baseline: 1.7425x; 1.7425x over previous
#include <cuda_runtime.h>
#include <cuda_fp16.h>
#include <math.h>
#include <stdint.h>

#define NN      50000
#define IN_DIM  128
#define OUT_DIM 32
#define HEADS   8
#define FF      256          // OUT_DIM * HEADS
#define EE      800000
#define SEM_HID 128
#define NCHUNK  49           // ceil(NN / 1024)

// ---------------- scratch (static device globals; no allocation) -------------
__device__ __half g_feat16[2][NN * FF];    // W-projected features (fp16, agg-only)
__device__ __half g_z16[2][NN * FF];       // z (fp16) = ELU(agg + bias)
__device__ float  g_el[2][NN * HEADS];
__device__ float  g_er[2][NN * HEADS];
__device__ int    g_csrc[2][EE];           // CSR src node per slot
__device__ int    g_rowptr[2][NN + 1];
__device__ int    g_cnt[2][NN];            // zero-init at load; re-zeroed by scanapply
__device__ int    g_cursor[2][NN];
__device__ int    g_bsum[2][NCHUNK];
__device__ float  g_qsum[2];               // zero-init at load; re-zeroed by count

// ---------------- mma helpers -------------------------------------------------
__device__ __forceinline__ uint32_t f2tf32(float x) {
    uint32_t r;
    asm("cvt.rna.tf32.f32 %0, %1;" : "=r"(r) : "f"(x));
    return r;
}
__device__ __forceinline__ void mma_tf32(float c[4],
                                         uint32_t a0, uint32_t a1, uint32_t a2, uint32_t a3,
                                         uint32_t b0, uint32_t b1) {
    asm volatile(
        "mma.sync.aligned.m16n8k8.row.col.f32.tf32.tf32.f32 "
        "{%0,%1,%2,%3}, {%4,%5,%6,%7}, {%8,%9}, {%0,%1,%2,%3};\n"
        : "+f"(c[0]), "+f"(c[1]), "+f"(c[2]), "+f"(c[3])
        : "r"(a0), "r"(a1), "r"(a2), "r"(a3), "r"(b0), "r"(b1));
}
__device__ __forceinline__ void mma_f16(float c[4],
                                        uint32_t a0, uint32_t a1, uint32_t a2, uint32_t a3,
                                        uint32_t b0, uint32_t b1) {
    asm volatile(
        "mma.sync.aligned.m16n8k16.row.col.f32.f16.f16.f32 "
        "{%0,%1,%2,%3}, {%4,%5,%6,%7}, {%8,%9}, {%0,%1,%2,%3};\n"
        : "+f"(c[0]), "+f"(c[1]), "+f"(c[2]), "+f"(c[3])
        : "r"(a0), "r"(a1), "r"(a2), "r"(a3), "r"(b0), "r"(b1));
}
__device__ __forceinline__ float tanh_fast(float x) {
    float r;
    asm("tanh.approx.f32 %0, %1;" : "=f"(r) : "f"(x));
    return r;
}

// ---------------- K1: tf32 GEMM  feat = h @ [W_a|W_b]  + fused el/er ---------
#define GBM 128
#define GBN 64
#define GBK 16
#define APAD 8
#define BPAD 8
__global__ __launch_bounds__(256) void gemm1_kernel(
    const float* __restrict__ h,
    const float* __restrict__ Wa,
    const float* __restrict__ Wb,
    const float* __restrict__ al_a,
    const float* __restrict__ ar_a,
    const float* __restrict__ al_b,
    const float* __restrict__ ar_b) {
    __shared__ uint32_t As[GBK][GBM + APAD];
    __shared__ uint32_t Bs[GBK][GBN + BPAD];
    const int tid = threadIdx.x;
    const int lane = tid & 31;
    const int wid = tid >> 5;
    const int mBase = (wid >> 1) * 32;
    const int nBase = (wid & 1) * 32;
    const int rowBase = blockIdx.y * GBM;
    const int colBase = blockIdx.x * GBN;

    float acc[2][4][4];
#pragma unroll
    for (int mf = 0; mf < 2; mf++)
#pragma unroll
        for (int nf = 0; nf < 4; nf++)
#pragma unroll
            for (int c = 0; c < 4; c++) acc[mf][nf][c] = 0.0f;

    for (int k0 = 0; k0 < IN_DIM; k0 += GBK) {
#pragma unroll
        for (int it = 0; it < 2; it++) {
            int idx = tid + it * 256;
            int r = idx >> 2, c4 = idx & 3;
            int gr = rowBase + r;
            float4 v = make_float4(0.f, 0.f, 0.f, 0.f);
            if (gr < NN) v = *(const float4*)&h[gr * IN_DIM + k0 + c4 * 4];
            As[c4 * 4 + 0][r] = f2tf32(v.x);
            As[c4 * 4 + 1][r] = f2tf32(v.y);
            As[c4 * 4 + 2][r] = f2tf32(v.z);
            As[c4 * 4 + 3][r] = f2tf32(v.w);
        }
        {
            int r = tid >> 4, c4 = tid & 15;
            int gc = colBase + c4 * 4;
            const float* W = (gc >= FF) ? Wb : Wa;
            int cc = gc & (FF - 1);
            float4 v = *(const float4*)&W[(k0 + r) * FF + cc];
            Bs[r][c4 * 4 + 0] = f2tf32(v.x);
            Bs[r][c4 * 4 + 1] = f2tf32(v.y);
            Bs[r][c4 * 4 + 2] = f2tf32(v.z);
            Bs[r][c4 * 4 + 3] = f2tf32(v.w);
        }
        __syncthreads();
#pragma unroll
        for (int ks = 0; ks < GBK; ks += 8) {
            uint32_t a[2][4], b[4][2];
#pragma unroll
            for (int mf = 0; mf < 2; mf++) {
                int row = mBase + mf * 16 + (lane >> 2);
                a[mf][0] = As[ks + (lane & 3)][row];
                a[mf][1] = As[ks + (lane & 3)][row + 8];
                a[mf][2] = As[ks + 4 + (lane & 3)][row];
                a[mf][3] = As[ks + 4 + (lane & 3)][row + 8];
            }
#pragma unroll
            for (int nf = 0; nf < 4; nf++) {
                int col = nBase + nf * 8 + (lane >> 2);
                b[nf][0] = Bs[ks + (lane & 3)][col];
                b[nf][1] = Bs[ks + 4 + (lane & 3)][col];
            }
#pragma unroll
            for (int mf = 0; mf < 2; mf++)
#pragma unroll
                for (int nf = 0; nf < 4; nf++)
                    mma_tf32(acc[mf][nf], a[mf][0], a[mf][1], a[mf][2], a[mf][3],
                             b[nf][0], b[nf][1]);
        }
        __syncthreads();
    }

    // ---- epilogue: write feat (fp16) + fused el/er (warp N-span == one head)
    const int gc0 = colBase + nBase;          // 32-aligned
    const int hg = gc0 >> 5;                  // global head 0..15
    const int p = hg >> 3;
    const int hd = hg & 7;
    const float* al = p ? al_b : al_a;
    const float* ar = p ? ar_b : ar_a;
    float alv[8], arv[8];
#pragma unroll
    for (int nf = 0; nf < 4; nf++) {
        int c = nf * 8 + 2 * (lane & 3);
        alv[nf * 2 + 0] = al[hd * OUT_DIM + c];
        alv[nf * 2 + 1] = al[hd * OUT_DIM + c + 1];
        arv[nf * 2 + 0] = ar[hd * OUT_DIM + c];
        arv[nf * 2 + 1] = ar[hd * OUT_DIM + c + 1];
    }
    const int ccBase = gc0 & 255;
#pragma unroll
    for (int mf = 0; mf < 2; mf++) {
#pragma unroll
        for (int half = 0; half < 2; half++) {
            int gr = rowBase + mBase + mf * 16 + half * 8 + (lane >> 2);
            float el = 0.0f, er = 0.0f;
            if (gr < NN) {
#pragma unroll
                for (int nf = 0; nf < 4; nf++) {
                    float v0 = acc[mf][nf][half * 2 + 0];
                    float v1 = acc[mf][nf][half * 2 + 1];
                    int cc = ccBase + nf * 8 + 2 * (lane & 3);
                    *(__half2*)&g_feat16[p][gr * FF + cc] = __floats2half2_rn(v0, v1);
                    el += v0 * alv[nf * 2] + v1 * alv[nf * 2 + 1];
                    er += v0 * arv[nf * 2] + v1 * arv[nf * 2 + 1];
                }
            }
            el += __shfl_xor_sync(0xffffffffu, el, 1);
            el += __shfl_xor_sync(0xffffffffu, el, 2);
            er += __shfl_xor_sync(0xffffffffu, er, 1);
            er += __shfl_xor_sync(0xffffffffu, er, 2);
            if ((lane & 3) == 0 && gr < NN) {
                g_el[p][gr * HEADS + hd] = el;
                g_er[p][gr * HEADS + hd] = er;
            }
        }
    }
}

// ---------------- K3: degree histogram (+ qsum reset) ------------------------
__global__ void count_kernel(const int* __restrict__ dst_a,
                             const int* __restrict__ dst_b) {
    int i = blockIdx.x * blockDim.x + threadIdx.x;
    if (i < 2) g_qsum[i] = 0.0f;          // reset for this replay (precedes gemm2)
    if (i >= 2 * EE) return;
    int p = (i >= EE) ? 1 : 0;
    int e = i - p * EE;
    int d = p ? dst_b[e] : dst_a[e];
    atomicAdd(&g_cnt[p][d], 1);
}

// ---------------- K4a: per-chunk reduce --------------------------------------
__global__ __launch_bounds__(256) void reduce_kernel() {
    int p = blockIdx.y, c = blockIdx.x, t = threadIdx.x;
    int base = c * 1024;
    int v = 0;
#pragma unroll
    for (int k = 0; k < 4; k++) {
        int i = base + t + k * 256;
        if (i < NN) v += g_cnt[p][i];
    }
    __shared__ int sh[256];
    sh[t] = v;
    __syncthreads();
#pragma unroll
    for (int st = 128; st > 0; st >>= 1) {
        if (t < st) sh[t] += sh[t + st];
        __syncthreads();
    }
    if (t == 0) g_bsum[p][c] = sh[0];
}

// ---------------- K4b: tiny serial scan of chunk sums ------------------------
__global__ void bscan_kernel() {
    int p = blockIdx.x;
    if (threadIdx.x != 0) return;
    int run = 0;
    for (int c = 0; c < NCHUNK; c++) {
        int tmp = g_bsum[p][c];
        g_bsum[p][c] = run;
        run += tmp;
    }
}

// ---------------- K4c: scan apply -> rowptr + cursor (+ cnt reset) -----------
__global__ __launch_bounds__(1024) void scanapply_kernel() {
    int p = blockIdx.y, c = blockIdx.x, t = threadIdx.x;
    int i = c * 1024 + t;
    int v = (i < NN) ? g_cnt[p][i] : 0;
    int lane = t & 31, w = t >> 5;
    int x = v;
#pragma unroll
    for (int o = 1; o < 32; o <<= 1) {
        int y = __shfl_up_sync(0xffffffffu, x, o);
        if (lane >= o) x += y;
    }
    __shared__ int ws[32];
    if (lane == 31) ws[w] = x;
    __syncthreads();
    if (w == 0) {
        int y = ws[lane];
#pragma unroll
        for (int o = 1; o < 32; o <<= 1) {
            int z = __shfl_up_sync(0xffffffffu, y, o);
            if (lane >= o) y += z;
        }
        ws[lane] = y;
    }
    __syncthreads();
    int incl = x + ((w > 0) ? ws[w - 1] : 0) + g_bsum[p][c];
    if (i < NN) {
        g_rowptr[p][i + 1] = incl;
        g_cursor[p][i]     = incl - v;
        g_cnt[p][i]        = 0;           // reset for next replay
    }
    if (i == 0) g_rowptr[p][0] = 0;
}

// ---------------- K5: scatter into CSR (slim: cursor + csrc only) ------------
__global__ void scatter_kernel(const int* __restrict__ src_a,
                               const int* __restrict__ dst_a,
                               const int* __restrict__ src_b,
                               const int* __restrict__ dst_b) {
    int i = blockIdx.x * blockDim.x + threadIdx.x;
    if (i >= 2 * EE) return;
    int p = (i >= EE) ? 1 : 0;
    int e = i - p * EE;
    int s = p ? src_b[e] : src_a[e];
    int d = p ? dst_b[e] : dst_a[e];
    int pos = atomicAdd(&g_cursor[p][d], 1);
    g_csrc[p][pos] = s;
}

// ---------------- K6: per-dst aggregation + softmax + bias + ELU -------------
// 128 threads per block; 2 dsts per block; 64 threads per (dst, metapath).
// R9 structure (direct loads, broadcast el) + 4-edge unroll for MLP.
__global__ __launch_bounds__(128) void agg_kernel(const float* __restrict__ bias_a,
                                                  const float* __restrict__ bias_b) {
    const int d = blockIdx.x * 2 + (threadIdx.x >> 6);
    const int p = blockIdx.y;
    const int t = threadIdx.x & 63;          // 0..63
    const int start = g_rowptr[p][d];
    const int end   = g_rowptr[p][d + 1];
    const int hd = t >> 3;                   // head for cols [t*4, t*4+4)

    const float er = __ldg(&g_er[p][d * HEADS + hd]);
    const __half* fbase  = &g_feat16[p][0];
    const float*  elbase = &g_el[p][0];
    const int*    csrc   = &g_csrc[p][0];

    float4 acc = make_float4(0.f, 0.f, 0.f, 0.f);
    float den = 0.0f;

    int j = start;
    for (; j + 3 < end; j += 4) {
        int s0 = csrc[j];
        int s1 = csrc[j + 1];
        int s2 = csrc[j + 2];
        int s3 = csrc[j + 3];
        float el0 = __ldg(&elbase[s0 * HEADS + hd]);
        float el1 = __ldg(&elbase[s1 * HEADS + hd]);
        float el2 = __ldg(&elbase[s2 * HEADS + hd]);
        float el3 = __ldg(&elbase[s3 * HEADS + hd]);
        uint2 r0 = *(const uint2*)&fbase[s0 * FF + t * 4];
        uint2 r1 = *(const uint2*)&fbase[s1 * FF + t * 4];
        uint2 r2 = *(const uint2*)&fbase[s2 * FF + t * 4];
        uint2 r3 = *(const uint2*)&fbase[s3 * FF + t * 4];
        float x0 = el0 + er; x0 = (x0 > 0.0f) ? x0 : 0.2f * x0;
        float x1 = el1 + er; x1 = (x1 > 0.0f) ? x1 : 0.2f * x1;
        float x2 = el2 + er; x2 = (x2 > 0.0f) ? x2 : 0.2f * x2;
        float x3 = el3 + er; x3 = (x3 > 0.0f) ? x3 : 0.2f * x3;
        float ex0 = __expf(x0);
        float ex1 = __expf(x1);
        float ex2 = __expf(x2);
        float ex3 = __expf(x3);
        den += (ex0 + ex1) + (ex2 + ex3);
        float2 a0 = __half22float2(*(const __half2*)&r0.x);
        float2 b0 = __half22float2(*(const __half2*)&r0.y);
        float2 a1 = __half22float2(*(const __half2*)&r1.x);
        float2 b1 = __half22float2(*(const __half2*)&r1.y);
        float2 a2 = __half22float2(*(const __half2*)&r2.x);
        float2 b2 = __half22float2(*(const __half2*)&r2.y);
        float2 a3 = __half22float2(*(const __half2*)&r3.x);
        float2 b3 = __half22float2(*(const __half2*)&r3.y);
        acc.x += (a0.x * ex0 + a1.x * ex1) + (a2.x * ex2 + a3.x * ex3);
        acc.y += (a0.y * ex0 + a1.y * ex1) + (a2.y * ex2 + a3.y * ex3);
        acc.z += (b0.x * ex0 + b1.x * ex1) + (b2.x * ex2 + b3.x * ex3);
        acc.w += (b0.y * ex0 + b1.y * ex1) + (b2.y * ex2 + b3.y * ex3);
    }
    for (; j < end; j++) {
        int s0 = csrc[j];
        float el0 = __ldg(&elbase[s0 * HEADS + hd]);
        uint2 r0 = *(const uint2*)&fbase[s0 * FF + t * 4];
        float x0 = el0 + er; x0 = (x0 > 0.0f) ? x0 : 0.2f * x0;
        float ex0 = __expf(x0);
        den += ex0;
        float2 a0 = __half22float2(*(const __half2*)&r0.x);
        float2 b0 = __half22float2(*(const __half2*)&r0.y);
        acc.x += a0.x * ex0;
        acc.y += a0.y * ex0;
        acc.z += b0.x * ex0;
        acc.w += b0.y * ex0;
    }

    float invd = (den > 0.0f) ? 1.0f / den : 1.0f;
    const float* bias = p ? bias_b : bias_a;
    float4 bv = *(const float4*)&bias[t * 4];
    float4 z;
    z.x = acc.x * invd + bv.x;
    z.y = acc.y * invd + bv.y;
    z.z = acc.z * invd + bv.z;
    z.w = acc.w * invd + bv.w;
    z.x = (z.x > 0.0f) ? z.x : (expf(z.x) - 1.0f);
    z.y = (z.y > 0.0f) ? z.y : (expf(z.y) - 1.0f);
    z.z = (z.z > 0.0f) ? z.z : (expf(z.z) - 1.0f);
    z.w = (z.w > 0.0f) ? z.w : (expf(z.w) - 1.0f);
    uint2 zo;
    *(__half2*)&zo.x = __floats2half2_rn(z.x, z.y);
    *(__half2*)&zo.y = __floats2half2_rn(z.z, z.w);
    *(uint2*)&g_z16[p][d * FF + t * 4] = zo;
}

// ---------------- K7: fp16 GEMM  q = Z @ Wsem  + fused tanh.wsem reduce ------
#define BK2   32
#define APAD2 8
#define BPAD2 8
__global__ __launch_bounds__(256) void gemm2_kernel(
    const float* __restrict__ Wsem,
    const float* __restrict__ bsem,
    const float* __restrict__ wsem) {
    __shared__ __half As[GBM][BK2 + APAD2];   // m-major
    __shared__ __half Bs[GBN][BK2 + BPAD2];   // n-major (transposed fill)
    const __half* Z = (const __half*)g_z16;
    const int M = 2 * NN;
    const int tid = threadIdx.x;
    const int lane = tid & 31;
    const int wid = tid >> 5;
    const int mBase = (wid >> 1) * 32;
    const int nBase = (wid & 1) * 32;
    const int rowBase = blockIdx.y * GBM;
    const int colBase = blockIdx.x * GBN;

    float acc[2][4][4];
#pragma unroll
    for (int mf = 0; mf < 2; mf++)
#pragma unroll
        for (int nf = 0; nf < 4; nf++)
#pragma unroll
            for (int c = 0; c < 4; c++) acc[mf][nf][c] = 0.0f;

    for (int k0 = 0; k0 < FF; k0 += BK2) {
#pragma unroll
        for (int it = 0; it < 2; it++) {
            int idx = tid + it * 256;
            int r = idx >> 2, q = idx & 3;
            int gr = rowBase + r;
            uint4 v = make_uint4(0u, 0u, 0u, 0u);
            if (gr < M) v = *(const uint4*)&Z[gr * FF + k0 + q * 8];
            *(uint4*)&As[r][q * 8] = v;
        }
#pragma unroll
        for (int it = 0; it < 2; it++) {
            int slot = tid * 2 + it;
            int r = slot >> 4, c4 = slot & 15;
            float4 v = *(const float4*)&Wsem[(k0 + r) * SEM_HID + colBase + c4 * 4];
            Bs[c4 * 4 + 0][r] = __float2half_rn(v.x);
            Bs[c4 * 4 + 1][r] = __float2half_rn(v.y);
            Bs[c4 * 4 + 2][r] = __float2half_rn(v.z);
            Bs[c4 * 4 + 3][r] = __float2half_rn(v.w);
        }
        __syncthreads();
#pragma unroll
        for (int ks = 0; ks < BK2; ks += 16) {
            uint32_t a[2][4], b[4][2];
#pragma unroll
            for (int mf = 0; mf < 2; mf++) {
                int row = mBase + mf * 16 + (lane >> 2);
                int kc = ks + 2 * (lane & 3);
                a[mf][0] = *(const uint32_t*)&As[row][kc];
                a[mf][1] = *(const uint32_t*)&As[row + 8][kc];
                a[mf][2] = *(const uint32_t*)&As[row][kc + 8];
                a[mf][3] = *(const uint32_t*)&As[row + 8][kc + 8];
            }
#pragma unroll
            for (int nf = 0; nf < 4; nf++) {
                int col = nBase + nf * 8 + (lane >> 2);
                int kc = ks + 2 * (lane & 3);
                b[nf][0] = *(const uint32_t*)&Bs[col][kc];
                b[nf][1] = *(const uint32_t*)&Bs[col][kc + 8];
            }
#pragma unroll
            for (int mf = 0; mf < 2; mf++)
#pragma unroll
                for (int nf = 0; nf < 4; nf++)
                    mma_f16(acc[mf][nf], a[mf][0], a[mf][1], a[mf][2], a[mf][3],
                            b[nf][0], b[nf][1]);
        }
        __syncthreads();
    }

    // ---- epilogue: tanh(q + bsem) . wsem, reduce, atomic into g_qsum --------
    float bsv[8], wsv[8];
#pragma unroll
    for (int nf = 0; nf < 4; nf++) {
        int gc = colBase + nBase + nf * 8 + 2 * (lane & 3);
        bsv[nf * 2 + 0] = bsem[gc];
        bsv[nf * 2 + 1] = bsem[gc + 1];
        wsv[nf * 2 + 0] = wsem[gc];
        wsv[nf * 2 + 1] = wsem[gc + 1];
    }
    float sp0 = 0.0f, sp1 = 0.0f;
#pragma unroll
    for (int mf = 0; mf < 2; mf++) {
#pragma unroll
        for (int half = 0; half < 2; half++) {
            int gr = rowBase + mBase + mf * 16 + half * 8 + (lane >> 2);
            if (gr < M) {
                float rs = 0.0f;
#pragma unroll
                for (int nf = 0; nf < 4; nf++) {
                    rs += tanh_fast(acc[mf][nf][half * 2 + 0] + bsv[nf * 2 + 0]) * wsv[nf * 2 + 0];
                    rs += tanh_fast(acc[mf][nf][half * 2 + 1] + bsv[nf * 2 + 1]) * wsv[nf * 2 + 1];
                }
                if (gr < NN) sp0 += rs; else sp1 += rs;
            }
        }
    }
#pragma unroll
    for (int o = 16; o > 0; o >>= 1) {
        sp0 += __shfl_down_sync(0xffffffffu, sp0, o);
        sp1 += __shfl_down_sync(0xffffffffu, sp1, o);
    }
    __shared__ float sh[8][2];
    if (lane == 0) { sh[wid][0] = sp0; sh[wid][1] = sp1; }
    __syncthreads();
    if (tid == 0) {
        float s0 = 0.f, s1 = 0.f;
#pragma unroll
        for (int k = 0; k < 8; k++) { s0 += sh[k][0]; s1 += sh[k][1]; }
        if (s0 != 0.0f) atomicAdd(&g_qsum[0], s0);
        if (s1 != 0.0f) atomicAdd(&g_qsum[1], s1);
    }
}

// ---------------- K9: combine with semantic softmax (fp16 z -> fp32 out) -----
__global__ void combine_kernel(float4* __restrict__ out) {
    int i = blockIdx.x * blockDim.x + threadIdx.x;
    if (i >= NN * FF / 4) return;
    float q0 = g_qsum[0] * (1.0f / NN);
    float q1 = g_qsum[1] * (1.0f / NN);
    float mx = fmaxf(q0, q1);
    float b0 = __expf(q0 - mx);
    float b1 = __expf(q1 - mx);
    float inv = 1.0f / (b0 + b1);
    b0 *= inv; b1 *= inv;
    uint2 u0 = *(const uint2*)&g_z16[0][i * 4];
    uint2 u1 = *(const uint2*)&g_z16[1][i * 4];
    float2 a0 = __half22float2(*(const __half2*)&u0.x);
    float2 a1 = __half22float2(*(const __half2*)&u0.y);
    float2 c0 = __half22float2(*(const __half2*)&u1.x);
    float2 c1 = __half22float2(*(const __half2*)&u1.y);
    float4 r;
    r.x = a0.x * b0 + c0.x * b1;
    r.y = a0.y * b0 + c0.y * b1;
    r.z = a1.x * b0 + c1.x * b1;
    r.w = a1.y * b0 + c1.y * b1;
    out[i] = r;
}

// ---------------- launch -----------------------------------------------------
extern "C" void kernel_launch(void* const* d_in, const int* in_sizes, int n_in,
                              void* d_out, int out_size) {
    const float* h      = (const float*)d_in[0];
    const int*   src_a  = (const int*)  d_in[1];
    const int*   dst_a  = (const int*)  d_in[2];
    const int*   src_b  = (const int*)  d_in[3];
    const int*   dst_b  = (const int*)  d_in[4];
    const float* W_a    = (const float*)d_in[5];
    const float* al_a   = (const float*)d_in[6];
    const float* ar_a   = (const float*)d_in[7];
    const float* bias_a = (const float*)d_in[8];
    const float* W_b    = (const float*)d_in[9];
    const float* al_b   = (const float*)d_in[10];
    const float* ar_b   = (const float*)d_in[11];
    const float* bias_b = (const float*)d_in[12];
    const float* Wsem   = (const float*)d_in[13];
    const float* bsem   = (const float*)d_in[14];
    const float* wsem   = (const float*)d_in[15];
    float* out = (float*)d_out;

    (void)in_sizes; (void)n_in; (void)out_size;

    // One-time creation of side stream + events (host objects, no device mem).
    static cudaStream_t s2 = nullptr;
    static cudaEvent_t ev_fork = nullptr, ev_join = nullptr;
    if (s2 == nullptr) {
        cudaStreamCreateWithFlags(&s2, cudaStreamNonBlocking);
        cudaEventCreateWithFlags(&ev_fork, cudaEventDisableTiming);
        cudaEventCreateWithFlags(&ev_join, cudaEventDisableTiming);
    }

    // ---- fork: CSR build on s2, projection GEMM on main stream --------------
    cudaEventRecord(ev_fork, 0);
    cudaStreamWaitEvent(s2, ev_fork, 0);

    // s2 branch: count -> scan -> scatter (depends only on edge lists)
    count_kernel<<<(2 * EE + 255) / 256, 256, 0, s2>>>(dst_a, dst_b);
    {
        dim3 grid(NCHUNK, 2);
        reduce_kernel<<<grid, 256, 0, s2>>>();
        bscan_kernel<<<2, 32, 0, s2>>>();
        scanapply_kernel<<<grid, 1024, 0, s2>>>();
    }
    scatter_kernel<<<(2 * EE + 255) / 256, 256, 0, s2>>>(src_a, dst_a, src_b, dst_b);
    cudaEventRecord(ev_join, s2);

    // main branch: projection GEMM (tf32 TC) + fused el/er
    {
        dim3 grid((2 * FF) / GBN, (NN + GBM - 1) / GBM);
        gemm1_kernel<<<grid, 256>>>(h, W_a, W_b, al_a, ar_a, al_b, ar_b);
    }

    // ---- join ----------------------------------------------------------------
    cudaStreamWaitEvent(0, ev_join, 0);

    {   // gather aggregation + softmax + bias + ELU (2 dsts per block)
        dim3 grid(NN / 2, 2);
        agg_kernel<<<grid, 128>>>(bias_a, bias_b);
    }

    {   // semantic GEMM (fp16 TC) + fused tanh.wsem reduction
        dim3 grid(SEM_HID / GBN, (2 * NN + GBM - 1) / GBM);
        gemm2_kernel<<<grid, 256>>>(Wsem, bsem, wsem);
    }

    combine_kernel<<<(NN * FF / 4 + 255) / 256, 256>>>((float4*)out);
}